// round 5
// baseline (speedup 1.0000x reference)
#include <cuda_runtime.h>
#include <math.h>

#define BB 2
#define NN 2048
#define DD 256
#define HH 8
#define NPAIRS (BB*NN*NN)          // 8388608
#define RANK_LO 7969176LL          // floor(0.95*(NPAIRS-1)), frac = 0.65

typedef unsigned long long ull;

// ---------------- f32x2 packed helpers (sm_100+ PTX) ------------------------------
__device__ __forceinline__ ull pk2(float lo, float hi) {
    ull r;
    asm("mov.b64 %0, {%1, %2};" : "=l"(r) : "r"(__float_as_uint(lo)), "r"(__float_as_uint(hi)));
    return r;
}
__device__ __forceinline__ void upk2(ull v, float& lo, float& hi) {
    unsigned a, b;
    asm("mov.b64 {%0, %1}, %2;" : "=r"(a), "=r"(b) : "l"(v));
    lo = __uint_as_float(a); hi = __uint_as_float(b);
}
__device__ __forceinline__ ull ffma2(ull a, ull b, ull c) {
    ull d;
    asm("fma.rn.f32x2 %0, %1, %2, %3;" : "=l"(d) : "l"(a), "l"(b), "l"(c));
    return d;
}

// ---------------- scratch (device globals; no dynamic allocation) ----------------
__device__ float g_q[BB*NN*DD];
__device__ float g_k[BB*NN*DD];
__device__ float g_kT[BB*HH*32*NN];     // [b][h][d][j]
__device__ float g_v[BB*NN*DD];
__device__ float g_att[BB*NN*DD];
__device__ float g_r[NPAIRS];
__device__ float g_scores[(size_t)BB*NN*HH*NN];   // 268 MB
__device__ float g_WqT[DD*DD];
__device__ float g_WkT[DD*DD];
__device__ float g_WvT[DD*DD];
__device__ float g_WoT[DD*DD];
__device__ float g_cos[NN*16];
__device__ float g_sin[NN*16];
__device__ unsigned g_h1[256];
__device__ unsigned g_h2[2][4096];
__device__ unsigned g_h3[2][4096];
__device__ unsigned g_pref1[2];
__device__ unsigned g_pref2[2];
__device__ long long g_rank2[2];
__device__ long long g_rank3[2];
__device__ float g_rend;

// ---------------- RoPE tables ------------------------------------------------------
__global__ void k_tables() {
    int idx = blockIdx.x * blockDim.x + threadIdx.x;   // NN*16
    int n = idx >> 4, f = idx & 15;
    double inv = pow(10000.0, -(double)f / 16.0);
    double ang = (double)n * inv;
    g_cos[idx] = (float)cos(ang);
    g_sin[idx] = (float)sin(ang);
}

// ---------------- transpose the 4 weight matrices ---------------------------------
__global__ void k_trans(const float* __restrict__ Wq, const float* __restrict__ Wk,
                        const float* __restrict__ Wv, const float* __restrict__ Wo) {
    int bid = blockIdx.x;            // 1024 blocks: 256 per matrix
    int m = bid >> 8;
    int d = bid & 255;
    int c = threadIdx.x;
    const float* src = (m == 0) ? Wq : (m == 1) ? Wk : (m == 2) ? Wv : Wo;
    float* dst = (m == 0) ? g_WqT : (m == 1) ? g_WkT : (m == 2) ? g_WvT : g_WoT;
    dst[c * DD + d] = src[d * DD + c];
}

// ---------------- zero histograms (graph replays!) --------------------------------
__global__ void k_zero() {
    int idx = blockIdx.x * blockDim.x + threadIdx.x;
    if (idx < 256) g_h1[idx] = 0;
    else if (idx < 256 + 8192) ((unsigned*)g_h2)[idx - 256] = 0;
    else if (idx < 256 + 16384) ((unsigned*)g_h3)[idx - 8448] = 0;
}

// ---------------- QKV projection + RoPE, 8 rows per block (R2 version) ------------
__global__ void k_qkv(const float* __restrict__ x) {
    __shared__ float xs[8][256];
    __shared__ float qs[8][256];
    __shared__ float ks[8][256];
    int r0 = blockIdx.x * 8;
    int t = threadIdx.x;
    #pragma unroll
    for (int r = 0; r < 8; r++) xs[r][t] = x[(r0 + r) * DD + t];
    __syncthreads();
    float aq[8], ak[8], av[8];
    #pragma unroll
    for (int r = 0; r < 8; r++) { aq[r] = 0.f; ak[r] = 0.f; av[r] = 0.f; }
    for (int c = 0; c < DD; c++) {
        float wq = g_WqT[c * DD + t];
        float wk = g_WkT[c * DD + t];
        float wv = g_WvT[c * DD + t];
        #pragma unroll
        for (int r = 0; r < 8; r++) {
            float xv = xs[r][c];
            aq[r] = fmaf(xv, wq, aq[r]);
            ak[r] = fmaf(xv, wk, ak[r]);
            av[r] = fmaf(xv, wv, av[r]);
        }
    }
    #pragma unroll
    for (int r = 0; r < 8; r++) { qs[r][t] = aq[r]; ks[r][t] = ak[r]; }
    __syncthreads();
    int dh = t & 31;
    int fi = dh & 15;
    bool lo = dh < 16;
    int partner = lo ? (t + 16) : (t - 16);
    #pragma unroll
    for (int r = 0; r < 8; r++) {
        int gr = r0 + r;
        int n = gr & (NN - 1);
        float cv = g_cos[n * 16 + fi];
        float sv = g_sin[n * 16 + fi];
        float qp = lo ? -qs[r][partner] : qs[r][partner];
        float kp = lo ? -ks[r][partner] : ks[r][partner];
        g_q[gr * DD + t] = qs[r][t] * cv + qp * sv;
        g_k[gr * DD + t] = ks[r][t] * cv + kp * sv;
        g_v[gr * DD + t] = av[r];
    }
}

// ---------------- K transpose to [b][h][d][j] -------------------------------------
__global__ void k_ktrans() {
    __shared__ float tile[32][33];
    int bh = blockIdx.y;             // b*HH + h
    int b = bh >> 3, h = bh & 7;
    int j0 = blockIdx.x * 32;
    int tx = threadIdx.x & 31, ty = threadIdx.x >> 5;   // 8 rows of 32
    #pragma unroll
    for (int r = ty; r < 32; r += 8)
        tile[r][tx] = g_k[(size_t)(b * NN + j0 + r) * DD + h * 32 + tx];
    __syncthreads();
    #pragma unroll
    for (int r = ty; r < 32; r += 8)
        g_kT[((size_t)(b * HH + h) * 32 + tx) * NN + j0 + r] = tile[r][tx];
}

// ---------------- pairwise r + fused top-8-bit histogram --------------------------
__global__ void k_r(const float* __restrict__ R_in, const float* __restrict__ t_in) {
    __shared__ float Rs[9], ts3[3];
    __shared__ unsigned hist[256];
    int i = blockIdx.x, b = blockIdx.y;
    int tid = threadIdx.x;
    hist[tid] = 0;
    if (tid < 9) Rs[tid] = R_in[(b * NN + i) * 9 + tid];
    if (tid < 3) ts3[tid] = t_in[(b * NN + i) * 3 + tid];
    __syncthreads();
    for (int j = tid; j < NN; j += 256) {
        float d0 = t_in[(b * NN + j) * 3 + 0] - ts3[0];
        float d1 = t_in[(b * NN + j) * 3 + 1] - ts3[1];
        float d2 = t_in[(b * NN + j) * 3 + 2] - ts3[2];
        float e0 = Rs[0] * d0 + Rs[3] * d1 + Rs[6] * d2;
        float e1 = Rs[1] * d0 + Rs[4] * d1 + Rs[7] * d2;
        float e2 = Rs[2] * d0 + Rs[5] * d1 + Rs[8] * d2;
        float r = fmaxf(sqrtf(e0 * e0 + e1 * e1 + e2 * e2), 1e-8f);
        g_r[(size_t)(b * NN + i) * NN + j] = r;
        atomicAdd(&hist[__float_as_uint(r) >> 24], 1u);
    }
    __syncthreads();
    if (hist[tid]) atomicAdd(&g_h1[tid], hist[tid]);
}

// ---------------- radix select scans ----------------------------------------------
__global__ void k_scanA() {
    if (threadIdx.x == 0) {
        long long cum = 0;
        for (int bkt = 0; bkt < 256; bkt++) {
            unsigned c = g_h1[bkt];
            #pragma unroll
            for (int sdx = 0; sdx < 2; sdx++) {
                long long rk = RANK_LO + sdx;
                if (rk >= cum && rk < cum + (long long)c) {
                    g_pref1[sdx] = (unsigned)bkt;
                    g_rank2[sdx] = rk - cum;
                }
            }
            cum += c;
        }
    }
}

__global__ void k_histB() {
    __shared__ unsigned h[2][4096];
    int tid = threadIdx.x;
    for (int u = tid; u < 8192; u += 256) ((unsigned*)h)[u] = 0;
    __syncthreads();
    unsigned p0 = g_pref1[0], p1 = g_pref1[1];
    int idx = blockIdx.x * blockDim.x + tid;
    int stride = gridDim.x * blockDim.x;
    for (; idx < NPAIRS; idx += stride) {
        unsigned u = __float_as_uint(g_r[idx]);
        unsigned hi = u >> 24;
        unsigned mid = (u >> 12) & 0xFFF;
        if (hi == p0) atomicAdd(&h[0][mid], 1u);
        if (hi == p1) atomicAdd(&h[1][mid], 1u);
    }
    __syncthreads();
    for (int u = tid; u < 8192; u += 256) {
        unsigned c = ((unsigned*)h)[u];
        if (c) atomicAdd(&((unsigned*)g_h2)[u], c);
    }
}

__global__ void k_scanB() {
    int sdx = threadIdx.x;
    if (sdx < 2) {
        long long cum = 0, rk = g_rank2[sdx];
        for (int bkt = 0; bkt < 4096; bkt++) {
            unsigned c = g_h2[sdx][bkt];
            if (rk >= cum && rk < cum + (long long)c) {
                g_pref2[sdx] = (unsigned)bkt;
                g_rank3[sdx] = rk - cum;
            }
            cum += c;
        }
    }
}

__global__ void k_histC() {
    __shared__ unsigned h[2][4096];
    int tid = threadIdx.x;
    for (int u = tid; u < 8192; u += 256) ((unsigned*)h)[u] = 0;
    __syncthreads();
    unsigned q0 = (g_pref1[0] << 12) | g_pref2[0];
    unsigned q1 = (g_pref1[1] << 12) | g_pref2[1];
    int idx = blockIdx.x * blockDim.x + tid;
    int stride = gridDim.x * blockDim.x;
    for (; idx < NPAIRS; idx += stride) {
        unsigned u = __float_as_uint(g_r[idx]);
        unsigned top20 = u >> 12;
        unsigned lowb = u & 0xFFF;
        if (top20 == q0) atomicAdd(&h[0][lowb], 1u);
        if (top20 == q1) atomicAdd(&h[1][lowb], 1u);
    }
    __syncthreads();
    for (int u = tid; u < 8192; u += 256) {
        unsigned c = ((unsigned*)h)[u];
        if (c) atomicAdd(&((unsigned*)g_h3)[u], c);
    }
}

__global__ void k_scanC() {
    __shared__ float val[2];
    int sdx = threadIdx.x;
    if (sdx < 2) {
        long long cum = 0, rk = g_rank3[sdx];
        for (int bkt = 0; bkt < 4096; bkt++) {
            unsigned c = g_h3[sdx][bkt];
            if (rk >= cum && rk < cum + (long long)c)
                val[sdx] = __uint_as_float((g_pref1[sdx] << 24) | (g_pref2[sdx] << 12) | (unsigned)bkt);
            cum += c;
        }
    }
    __syncthreads();
    if (sdx == 0) g_rend = val[0] + 0.65f * (val[1] - val[0]) + 1e-6f;
}

// ---------------- bias MLP + QK scores (hot kernel, f32x2 packed) -----------------
// 4 i-rows per thread as two f32x2 lanes. Layer-1 folded into per-(m,seg)
// (base,slope) table: preact = base + slope*r + W1e . ehat.
__global__ void __launch_bounds__(256) k_scores(
    const float* __restrict__ t_in, const float* __restrict__ R_in,
    const float* __restrict__ W1, const float* __restrict__ b1,
    const float* __restrict__ W2, const float* __restrict__ b2) {
    __shared__ float2 bs_s[64 * 17];          // (base, slope) per (m, seg)
    __shared__ float4 w1e_s[64];              // (e0, e1, e2, 0) packed -> 1 LDS.128
    __shared__ ull W2p_s[8 * 64];             // broadcast-packed W2
    __shared__ ull b2p_s[8];
    __shared__ ull q01p_s[256], q23p_s[256];  // packed q rows {il0,il1}, {il2,il3}
    __shared__ float Rs[4][9], ts4[4][3];
    int b = blockIdx.y;
    int i0 = blockIdx.x * 4;
    int tid = threadIdx.x;

    float rend = fmaxf(g_rend, 1e-6f);
    float tmul = 15.0f / rend;

    // build (base, slope) table: rbf contribution is linear in r per segment
    for (int u = tid; u < 64 * 17; u += 256) {
        int m = u / 17, s = u % 17;
        float w1r = W1[m * 20 + 0];
        float b1v = b1[m];
        float base, slope;
        if (s < 15) {
            float r0 = W1[m * 20 + 4 + s];
            float r1 = W1[m * 20 + 5 + s];
            float d = r1 - r0;
            base = b1v + r0 - (float)s * d;
            slope = w1r + d * tmul;
        } else if (s == 15) {
            float r15 = W1[m * 20 + 19];
            base = b1v + 16.0f * r15;
            slope = w1r - r15 * tmul;
        } else {
            base = b1v;
            slope = w1r;
        }
        bs_s[u] = make_float2(base, slope);
    }
    if (tid < 64)
        w1e_s[tid] = make_float4(W1[tid * 20 + 1], W1[tid * 20 + 2], W1[tid * 20 + 3], 0.0f);
    for (int u = tid; u < 512; u += 256) { float w = W2[u]; W2p_s[u] = pk2(w, w); }
    if (tid < 8) { float bv = b2[tid]; b2p_s[tid] = pk2(bv, bv); }
    {
        float q0 = g_q[(size_t)(b * NN + i0 + 0) * DD + tid];
        float q1 = g_q[(size_t)(b * NN + i0 + 1) * DD + tid];
        float q2 = g_q[(size_t)(b * NN + i0 + 2) * DD + tid];
        float q3 = g_q[(size_t)(b * NN + i0 + 3) * DD + tid];
        q01p_s[tid] = pk2(q0, q1);
        q23p_s[tid] = pk2(q2, q3);
    }
    if (tid < 36) Rs[tid / 9][tid % 9] = R_in[(b * NN + i0 + tid / 9) * 9 + tid % 9];
    if (tid < 12) ts4[tid / 3][tid % 3] = t_in[(b * NN + i0 + tid / 3) * 3 + tid % 3];
    __syncthreads();

    const float scale = 0.17677669529663687f;    // 1/sqrt(32)
    const ull scale2 = pk2(scale, scale);

    for (int j = tid; j < NN; j += 256) {
        float tj0 = t_in[(b * NN + j) * 3 + 0];
        float tj1 = t_in[(b * NN + j) * 3 + 1];
        float tj2 = t_in[(b * NN + j) * 3 + 2];
        float rr[4], eh0[4], eh1[4], eh2[4];
        int seg[4];
        #pragma unroll
        for (int il = 0; il < 4; il++) {
            float d0 = tj0 - ts4[il][0], d1 = tj1 - ts4[il][1], d2 = tj2 - ts4[il][2];
            float e0 = Rs[il][0] * d0 + Rs[il][3] * d1 + Rs[il][6] * d2;
            float e1 = Rs[il][1] * d0 + Rs[il][4] * d1 + Rs[il][7] * d2;
            float e2 = Rs[il][2] * d0 + Rs[il][5] * d1 + Rs[il][8] * d2;
            float r = fmaxf(sqrtf(e0 * e0 + e1 * e1 + e2 * e2), 1e-8f);
            float inv = 1.0f / r;
            rr[il] = r;
            eh0[il] = e0 * inv; eh1[il] = e1 * inv; eh2[il] = e2 * inv;
            float tt = r * tmul;
            int s = (int)tt;
            if (s > 16) s = 16;
            if (s < 0) s = 0;
            seg[il] = s;
        }

        // ---- QK dots, packed over il pairs ----
        ull acc01[8], acc23[8];
        #pragma unroll
        for (int hh = 0; hh < 8; hh++) { acc01[hh] = 0ULL; acc23[hh] = 0ULL; }
        #pragma unroll
        for (int hh = 0; hh < 8; hh++) {
            const float* kp = g_kT + ((size_t)(b * HH + hh) * 32) * NN + j;
            ull a01 = acc01[hh], a23 = acc23[hh];
            #pragma unroll 8
            for (int d = 0; d < 32; d++) {
                float kv = kp[(size_t)d * NN];
                ull kv2 = pk2(kv, kv);
                a01 = ffma2(kv2, q01p_s[hh * 32 + d], a01);
                a23 = ffma2(kv2, q23p_s[hh * 32 + d], a23);
            }
            acc01[hh] = ffma2(a01, scale2, b2p_s[hh]);
            acc23[hh] = ffma2(a23, scale2, b2p_s[hh]);
        }

        // ---- MLP layer1 scalar (base/slope folded), layer2 packed ----
        for (int m = 0; m < 64; m++) {
            float4 we = w1e_s[m];
            float h[4];
            #pragma unroll
            for (int il = 0; il < 4; il++) {
                float2 bsv = bs_s[m * 17 + seg[il]];
                float a = fmaf(rr[il], bsv.y, bsv.x);
                a = fmaf(eh0[il], we.x, a);
                a = fmaf(eh1[il], we.y, a);
                a = fmaf(eh2[il], we.z, a);
                h[il] = fmaxf(a, 0.0f);
            }
            ull h01 = pk2(h[0], h[1]);
            ull h23 = pk2(h[2], h[3]);
            #pragma unroll
            for (int hh = 0; hh < 8; hh++) {
                ull w2p = W2p_s[hh * 64 + m];
                acc01[hh] = ffma2(h01, w2p, acc01[hh]);
                acc23[hh] = ffma2(h23, w2p, acc23[hh]);
            }
        }

        #pragma unroll
        for (int hh = 0; hh < 8; hh++) {
            float s0, s1, s2, s3;
            upk2(acc01[hh], s0, s1);
            upk2(acc23[hh], s2, s3);
            g_scores[((size_t)((b * NN + i0 + 0) * HH + hh)) * NN + j] = s0;
            g_scores[((size_t)((b * NN + i0 + 1) * HH + hh)) * NN + j] = s1;
            g_scores[((size_t)((b * NN + i0 + 2) * HH + hh)) * NN + j] = s2;
            g_scores[((size_t)((b * NN + i0 + 3) * HH + hh)) * NN + j] = s3;
        }
    }
}

// ---------------- warp reduce helpers ---------------------------------------------
__device__ __forceinline__ float warpMax(float v) {
    #pragma unroll
    for (int o = 16; o; o >>= 1) v = fmaxf(v, __shfl_xor_sync(0xFFFFFFFFu, v, o));
    return v;
}
__device__ __forceinline__ float warpSum(float v) {
    #pragma unroll
    for (int o = 16; o; o >>= 1) v += __shfl_xor_sync(0xFFFFFFFFu, v, o);
    return v;
}

// ---------------- fused softmax + AV (two-pass, 8 i-rows per block) ---------------
__global__ void __launch_bounds__(256) k_smav() {
    __shared__ float v_s[32 * 256];     // [jj][c]
    __shared__ float p_s[64 * 32];      // [row=il*8+h][jj]
    __shared__ float m_s[64], l_s[64];
    int bx = blockIdx.x;
    int b = bx >> 8;
    int i0 = (bx & 255) * 8;
    int tid = threadIdx.x;
    int wrp = tid >> 5, lane = tid & 31;

    // ---- phase 1: online per-row max + denominator, single scores read ----
    #pragma unroll
    for (int k = 0; k < 8; k++) {
        int row = k * 8 + wrp;          // il = k, h = wrp
        const float* ptr = g_scores + ((size_t)((b * NN + i0 + k) * HH + wrp)) * NN;
        float mx = -3.0e38f, sm = 0.0f;
        for (int j = lane; j < NN; j += 32) {
            float v = ptr[j];
            if (v > mx) { sm *= expf(mx - v); mx = v; }   // rare
            sm += expf(v - mx);
        }
        // merge lanes: global max, rescale partial sums
        float gm = warpMax(mx);
        sm *= expf(mx - gm);
        sm = warpSum(sm);
        if (lane == 0) { m_s[row] = gm; l_s[row] = sm; }
    }
    __syncthreads();

    // ---- phase 2: AV with exp-on-the-fly ----
    int h = wrp;
    float acc[8];
    #pragma unroll
    for (int il = 0; il < 8; il++) acc[il] = 0.0f;

    for (int j0 = 0; j0 < NN; j0 += 32) {
        __syncthreads();
        // v tile [32][256]
        #pragma unroll
        for (int k = 0; k < 32; k++) {
            int u = tid + k * 256;
            v_s[u] = g_v[(size_t)(b * NN + j0 + (u >> 8)) * DD + (u & 255)];
        }
        // p tile [64][32]
        #pragma unroll
        for (int k = 0; k < 8; k++) {
            int u = tid + k * 256;
            int row = u >> 5, jj = u & 31;
            float sc = g_scores[((size_t)((b * NN + i0 + (row >> 3)) * HH + (row & 7))) * NN + j0 + jj];
            p_s[u] = expf(sc - m_s[row]);
        }
        __syncthreads();
        #pragma unroll 4
        for (int jj = 0; jj < 32; jj++) {
            float vv = v_s[jj * 256 + tid];
            #pragma unroll
            for (int il = 0; il < 8; il++)
                acc[il] = fmaf(p_s[(il * 8 + h) * 32 + jj], vv, acc[il]);
        }
    }
    #pragma unroll
    for (int il = 0; il < 8; il++)
        g_att[(size_t)(b * NN + i0 + il) * DD + tid] = acc[il] / l_s[il * 8 + h];
}

// ---------------- final Wo projection ---------------------------------------------
__global__ void k_out(float* __restrict__ out) {
    __shared__ float xs[8][256];
    int r0 = blockIdx.x * 8;
    int t = threadIdx.x;
    #pragma unroll
    for (int r = 0; r < 8; r++) xs[r][t] = g_att[(size_t)(r0 + r) * DD + t];
    __syncthreads();
    float acc[8];
    #pragma unroll
    for (int r = 0; r < 8; r++) acc[r] = 0.f;
    for (int c = 0; c < DD; c++) {
        float w = g_WoT[c * DD + t];
        #pragma unroll
        for (int r = 0; r < 8; r++) acc[r] = fmaf(xs[r][c], w, acc[r]);
    }
    #pragma unroll
    for (int r = 0; r < 8; r++) out[(size_t)(r0 + r) * DD + t] = acc[r];
}

// ---------------- launch ----------------------------------------------------------
extern "C" void kernel_launch(void* const* d_in, const int* in_sizes, int n_in,
                              void* d_out, int out_size) {
    const float* x  = (const float*)d_in[0];
    const float* R  = (const float*)d_in[1];
    const float* t  = (const float*)d_in[2];
    // d_in[3] = node_mask (all true)
    const float* Wq = (const float*)d_in[4];
    const float* Wk = (const float*)d_in[5];
    const float* Wv = (const float*)d_in[6];
    const float* Wo = (const float*)d_in[7];
    const float* W1 = (const float*)d_in[8];
    const float* b1 = (const float*)d_in[9];
    const float* W2 = (const float*)d_in[10];
    const float* b2 = (const float*)d_in[11];
    float* out = (float*)d_out;

    k_tables<<<128, 256>>>();
    k_trans<<<1024, 256>>>(Wq, Wk, Wv, Wo);
    k_zero<<<65, 256>>>();
    // PROFILING PROBE: 4th launch lands in ncu's capture slot. Small-grid run of
    // the hot kernel; deterministic (zero-init globals / overwritten later).
    k_scores<<<dim3(32, 2), 256>>>(t, R, W1, b1, W2, b2);
    k_qkv<<<512, 256>>>(x);
    k_ktrans<<<dim3(64, 16), 256>>>();
    k_r<<<dim3(NN, BB), 256>>>(R, t);
    k_scanA<<<1, 32>>>();
    k_histB<<<1024, 256>>>();
    k_scanB<<<1, 32>>>();
    k_histC<<<1024, 256>>>();
    k_scanC<<<1, 32>>>();
    k_scores<<<dim3(NN / 4, BB), 256>>>(t, R, W1, b1, W2, b2);
    k_smav<<<512, 256>>>();
    k_out<<<512, 256>>>(out);
}

// round 6
// speedup vs baseline: 1.6490x; 1.6490x over previous
#include <cuda_runtime.h>
#include <math.h>

#define BB 2
#define NN 2048
#define DD 256
#define HH 8
#define NPAIRS (BB*NN*NN)          // 8388608
#define RANK_LO 7969176LL          // floor(0.95*(NPAIRS-1)), frac = 0.65

// ---------------- scratch (device globals; no dynamic allocation) ----------------
__device__ float g_q[BB*NN*DD];
__device__ float g_k[BB*NN*DD];
__device__ float g_kT[BB*HH*32*NN];     // [b][h][d][j]
__device__ float g_v[BB*NN*DD];
__device__ float g_att[BB*NN*DD];
__device__ float g_r[NPAIRS];
__device__ float g_scores[(size_t)BB*NN*HH*NN];   // 268 MB
__device__ float g_WqT[DD*DD];
__device__ float g_WkT[DD*DD];
__device__ float g_WvT[DD*DD];
__device__ float g_WoT[DD*DD];
__device__ float g_cos[NN*16];
__device__ float g_sin[NN*16];
__device__ unsigned g_h1[256];
__device__ unsigned g_h2[2][4096];
__device__ unsigned g_h3[2][4096];
__device__ unsigned g_pref1[2];
__device__ unsigned g_pref2[2];
__device__ long long g_rank2[2];
__device__ long long g_rank3[2];
__device__ float g_rend;

// ---------------- RoPE tables ------------------------------------------------------
__global__ void k_tables() {
    int idx = blockIdx.x * blockDim.x + threadIdx.x;   // NN*16
    int n = idx >> 4, f = idx & 15;
    double inv = pow(10000.0, -(double)f / 16.0);
    double ang = (double)n * inv;
    g_cos[idx] = (float)cos(ang);
    g_sin[idx] = (float)sin(ang);
}

// ---------------- transpose the 4 weight matrices ---------------------------------
__global__ void k_trans(const float* __restrict__ Wq, const float* __restrict__ Wk,
                        const float* __restrict__ Wv, const float* __restrict__ Wo) {
    int bid = blockIdx.x;            // 1024 blocks: 256 per matrix
    int m = bid >> 8;
    int d = bid & 255;
    int c = threadIdx.x;
    const float* src = (m == 0) ? Wq : (m == 1) ? Wk : (m == 2) ? Wv : Wo;
    float* dst = (m == 0) ? g_WqT : (m == 1) ? g_WkT : (m == 2) ? g_WvT : g_WoT;
    dst[c * DD + d] = src[d * DD + c];
}

// ---------------- zero histograms (graph replays!) --------------------------------
__global__ void k_zero() {
    int idx = blockIdx.x * blockDim.x + threadIdx.x;
    if (idx < 256) g_h1[idx] = 0;
    else if (idx < 256 + 8192) ((unsigned*)g_h2)[idx - 256] = 0;
    else if (idx < 256 + 16384) ((unsigned*)g_h3)[idx - 8448] = 0;
}

// ---------------- QKV projection + RoPE, 8 rows per block (R2 version) ------------
__global__ void k_qkv(const float* __restrict__ x) {
    __shared__ float xs[8][256];
    __shared__ float qs[8][256];
    __shared__ float ks[8][256];
    int r0 = blockIdx.x * 8;
    int t = threadIdx.x;
    #pragma unroll
    for (int r = 0; r < 8; r++) xs[r][t] = x[(r0 + r) * DD + t];
    __syncthreads();
    float aq[8], ak[8], av[8];
    #pragma unroll
    for (int r = 0; r < 8; r++) { aq[r] = 0.f; ak[r] = 0.f; av[r] = 0.f; }
    for (int c = 0; c < DD; c++) {
        float wq = g_WqT[c * DD + t];
        float wk = g_WkT[c * DD + t];
        float wv = g_WvT[c * DD + t];
        #pragma unroll
        for (int r = 0; r < 8; r++) {
            float xv = xs[r][c];
            aq[r] = fmaf(xv, wq, aq[r]);
            ak[r] = fmaf(xv, wk, ak[r]);
            av[r] = fmaf(xv, wv, av[r]);
        }
    }
    #pragma unroll
    for (int r = 0; r < 8; r++) { qs[r][t] = aq[r]; ks[r][t] = ak[r]; }
    __syncthreads();
    int dh = t & 31;
    int fi = dh & 15;
    bool lo = dh < 16;
    int partner = lo ? (t + 16) : (t - 16);
    #pragma unroll
    for (int r = 0; r < 8; r++) {
        int gr = r0 + r;
        int n = gr & (NN - 1);
        float cv = g_cos[n * 16 + fi];
        float sv = g_sin[n * 16 + fi];
        float qp = lo ? -qs[r][partner] : qs[r][partner];
        float kp = lo ? -ks[r][partner] : ks[r][partner];
        g_q[gr * DD + t] = qs[r][t] * cv + qp * sv;
        g_k[gr * DD + t] = ks[r][t] * cv + kp * sv;
        g_v[gr * DD + t] = av[r];
    }
}

// ---------------- K transpose to [b][h][d][j] -------------------------------------
__global__ void k_ktrans() {
    __shared__ float tile[32][33];
    int bh = blockIdx.y;             // b*HH + h
    int b = bh >> 3, h = bh & 7;
    int j0 = blockIdx.x * 32;
    int tx = threadIdx.x & 31, ty = threadIdx.x >> 5;   // 8 rows of 32
    #pragma unroll
    for (int r = ty; r < 32; r += 8)
        tile[r][tx] = g_k[(size_t)(b * NN + j0 + r) * DD + h * 32 + tx];
    __syncthreads();
    #pragma unroll
    for (int r = ty; r < 32; r += 8)
        g_kT[((size_t)(b * HH + h) * 32 + tx) * NN + j0 + r] = tile[r][tx];
}

// ---------------- pairwise r + fused top-8-bit histogram --------------------------
__global__ void k_r(const float* __restrict__ R_in, const float* __restrict__ t_in) {
    __shared__ float Rs[9], ts3[3];
    __shared__ unsigned hist[256];
    int i = blockIdx.x, b = blockIdx.y;
    int tid = threadIdx.x;
    hist[tid] = 0;
    if (tid < 9) Rs[tid] = R_in[(b * NN + i) * 9 + tid];
    if (tid < 3) ts3[tid] = t_in[(b * NN + i) * 3 + tid];
    __syncthreads();
    for (int j = tid; j < NN; j += 256) {
        float d0 = t_in[(b * NN + j) * 3 + 0] - ts3[0];
        float d1 = t_in[(b * NN + j) * 3 + 1] - ts3[1];
        float d2 = t_in[(b * NN + j) * 3 + 2] - ts3[2];
        float e0 = Rs[0] * d0 + Rs[3] * d1 + Rs[6] * d2;
        float e1 = Rs[1] * d0 + Rs[4] * d1 + Rs[7] * d2;
        float e2 = Rs[2] * d0 + Rs[5] * d1 + Rs[8] * d2;
        float r = fmaxf(sqrtf(e0 * e0 + e1 * e1 + e2 * e2), 1e-8f);
        g_r[(size_t)(b * NN + i) * NN + j] = r;
        atomicAdd(&hist[__float_as_uint(r) >> 24], 1u);
    }
    __syncthreads();
    if (hist[tid]) atomicAdd(&g_h1[tid], hist[tid]);
}

// ---------------- radix select scans ----------------------------------------------
__global__ void k_scanA() {
    if (threadIdx.x == 0) {
        long long cum = 0;
        for (int bkt = 0; bkt < 256; bkt++) {
            unsigned c = g_h1[bkt];
            #pragma unroll
            for (int sdx = 0; sdx < 2; sdx++) {
                long long rk = RANK_LO + sdx;
                if (rk >= cum && rk < cum + (long long)c) {
                    g_pref1[sdx] = (unsigned)bkt;
                    g_rank2[sdx] = rk - cum;
                }
            }
            cum += c;
        }
    }
}

__global__ void k_histB() {
    __shared__ unsigned h[2][4096];
    int tid = threadIdx.x;
    for (int u = tid; u < 8192; u += 256) ((unsigned*)h)[u] = 0;
    __syncthreads();
    unsigned p0 = g_pref1[0], p1 = g_pref1[1];
    int idx = blockIdx.x * blockDim.x + tid;
    int stride = gridDim.x * blockDim.x;
    for (; idx < NPAIRS; idx += stride) {
        unsigned u = __float_as_uint(g_r[idx]);
        unsigned hi = u >> 24;
        unsigned mid = (u >> 12) & 0xFFF;
        if (hi == p0) atomicAdd(&h[0][mid], 1u);
        if (hi == p1) atomicAdd(&h[1][mid], 1u);
    }
    __syncthreads();
    for (int u = tid; u < 8192; u += 256) {
        unsigned c = ((unsigned*)h)[u];
        if (c) atomicAdd(&((unsigned*)g_h2)[u], c);
    }
}

__global__ void k_scanB() {
    int sdx = threadIdx.x;
    if (sdx < 2) {
        long long cum = 0, rk = g_rank2[sdx];
        for (int bkt = 0; bkt < 4096; bkt++) {
            unsigned c = g_h2[sdx][bkt];
            if (rk >= cum && rk < cum + (long long)c) {
                g_pref2[sdx] = (unsigned)bkt;
                g_rank3[sdx] = rk - cum;
            }
            cum += c;
        }
    }
}

__global__ void k_histC() {
    __shared__ unsigned h[2][4096];
    int tid = threadIdx.x;
    for (int u = tid; u < 8192; u += 256) ((unsigned*)h)[u] = 0;
    __syncthreads();
    unsigned q0 = (g_pref1[0] << 12) | g_pref2[0];
    unsigned q1 = (g_pref1[1] << 12) | g_pref2[1];
    int idx = blockIdx.x * blockDim.x + tid;
    int stride = gridDim.x * blockDim.x;
    for (; idx < NPAIRS; idx += stride) {
        unsigned u = __float_as_uint(g_r[idx]);
        unsigned top20 = u >> 12;
        unsigned lowb = u & 0xFFF;
        if (top20 == q0) atomicAdd(&h[0][lowb], 1u);
        if (top20 == q1) atomicAdd(&h[1][lowb], 1u);
    }
    __syncthreads();
    for (int u = tid; u < 8192; u += 256) {
        unsigned c = ((unsigned*)h)[u];
        if (c) atomicAdd(&((unsigned*)g_h3)[u], c);
    }
}

__global__ void k_scanC() {
    __shared__ float val[2];
    int sdx = threadIdx.x;
    if (sdx < 2) {
        long long cum = 0, rk = g_rank3[sdx];
        for (int bkt = 0; bkt < 4096; bkt++) {
            unsigned c = g_h3[sdx][bkt];
            if (rk >= cum && rk < cum + (long long)c)
                val[sdx] = __uint_as_float((g_pref1[sdx] << 24) | (g_pref2[sdx] << 12) | (unsigned)bkt);
            cum += c;
        }
    }
    __syncthreads();
    if (sdx == 0) g_rend = val[0] + 0.65f * (val[1] - val[0]) + 1e-6f;
}

// ---------------- bias MLP + QK scores (hot kernel, scalar, occupancy-first) ------
// 4 i-rows per thread, scalar FFMA, <=128 regs (2 blocks/SM).
__global__ void __launch_bounds__(256, 2) k_scores(
    const float* __restrict__ t_in, const float* __restrict__ R_in,
    const float* __restrict__ W1, const float* __restrict__ b1,
    const float* __restrict__ W2, const float* __restrict__ b2) {
    __shared__ float2 bs_s[64 * 17];          // (base, slope) per (m, seg)
    __shared__ float4 w1e_s[64];              // (e0, e1, e2, 0)
    __shared__ float W2s[8 * 64];
    __shared__ float b2s[8];
    __shared__ float qs[4][256];
    __shared__ float Rs[4][9], ts4[4][3];
    int b = blockIdx.y;
    int i0 = blockIdx.x * 4;
    int tid = threadIdx.x;

    float rend = fmaxf(g_rend, 1e-6f);
    float tmul = 15.0f / rend;

    // (base, slope) table: rbf contribution is linear in r within each segment
    for (int u = tid; u < 64 * 17; u += 256) {
        int m = u / 17, s = u % 17;
        float w1r = W1[m * 20 + 0];
        float b1v = b1[m];
        float base, slope;
        if (s < 15) {
            float r0 = W1[m * 20 + 4 + s];
            float r1 = W1[m * 20 + 5 + s];
            float d = r1 - r0;
            base = b1v + r0 - (float)s * d;
            slope = w1r + d * tmul;
        } else if (s == 15) {
            float r15 = W1[m * 20 + 19];
            base = b1v + 16.0f * r15;
            slope = w1r - r15 * tmul;
        } else {
            base = b1v;
            slope = w1r;
        }
        bs_s[u] = make_float2(base, slope);
    }
    if (tid < 64)
        w1e_s[tid] = make_float4(W1[tid * 20 + 1], W1[tid * 20 + 2], W1[tid * 20 + 3], 0.0f);
    for (int u = tid; u < 512; u += 256) W2s[u] = W2[u];
    if (tid < 8) b2s[tid] = b2[tid];
    #pragma unroll
    for (int il = 0; il < 4; il++) qs[il][tid] = g_q[(size_t)(b * NN + i0 + il) * DD + tid];
    if (tid < 36) Rs[tid / 9][tid % 9] = R_in[(b * NN + i0 + tid / 9) * 9 + tid % 9];
    if (tid < 12) ts4[tid / 3][tid % 3] = t_in[(b * NN + i0 + tid / 3) * 3 + tid % 3];
    __syncthreads();

    const float scale = 0.17677669529663687f;    // 1/sqrt(32)

    for (int j = tid; j < NN; j += 256) {
        float tj0 = t_in[(b * NN + j) * 3 + 0];
        float tj1 = t_in[(b * NN + j) * 3 + 1];
        float tj2 = t_in[(b * NN + j) * 3 + 2];
        float rr[4], eh0[4], eh1[4], eh2[4];
        int seg[4];
        #pragma unroll
        for (int il = 0; il < 4; il++) {
            float d0 = tj0 - ts4[il][0], d1 = tj1 - ts4[il][1], d2 = tj2 - ts4[il][2];
            float e0 = Rs[il][0] * d0 + Rs[il][3] * d1 + Rs[il][6] * d2;
            float e1 = Rs[il][1] * d0 + Rs[il][4] * d1 + Rs[il][7] * d2;
            float e2 = Rs[il][2] * d0 + Rs[il][5] * d1 + Rs[il][8] * d2;
            float r = fmaxf(sqrtf(e0 * e0 + e1 * e1 + e2 * e2), 1e-8f);
            float inv = 1.0f / r;
            rr[il] = r;
            eh0[il] = e0 * inv; eh1[il] = e1 * inv; eh2[il] = e2 * inv;
            float tt = r * tmul;
            int s = (int)tt;
            if (s > 16) s = 16;
            if (s < 0) s = 0;
            seg[il] = s;
        }

        // ---- QK dots via transposed K (coalesced) ----
        float acc[4][8];
        #pragma unroll
        for (int il = 0; il < 4; il++)
            #pragma unroll
            for (int hh = 0; hh < 8; hh++) acc[il][hh] = 0.0f;
        #pragma unroll
        for (int hh = 0; hh < 8; hh++) {
            const float* kp = g_kT + ((size_t)(b * HH + hh) * 32) * NN + j;
            #pragma unroll 8
            for (int d = 0; d < 32; d++) {
                float kv = kp[(size_t)d * NN];
                #pragma unroll
                for (int il = 0; il < 4; il++)
                    acc[il][hh] = fmaf(kv, qs[il][hh * 32 + d], acc[il][hh]);
            }
        }
        #pragma unroll
        for (int il = 0; il < 4; il++)
            #pragma unroll
            for (int hh = 0; hh < 8; hh++)
                acc[il][hh] = fmaf(acc[il][hh], scale, b2s[hh]);

        // ---- MLP: folded layer-1 (base/slope + ehat), scalar layer-2 ----
        for (int m = 0; m < 64; m++) {
            float4 we = w1e_s[m];
            float h[4];
            #pragma unroll
            for (int il = 0; il < 4; il++) {
                float2 bsv = bs_s[m * 17 + seg[il]];
                float a = fmaf(rr[il], bsv.y, bsv.x);
                a = fmaf(eh0[il], we.x, a);
                a = fmaf(eh1[il], we.y, a);
                a = fmaf(eh2[il], we.z, a);
                h[il] = fmaxf(a, 0.0f);
            }
            #pragma unroll
            for (int hh = 0; hh < 8; hh++) {
                float w2v = W2s[hh * 64 + m];
                #pragma unroll
                for (int il = 0; il < 4; il++)
                    acc[il][hh] = fmaf(h[il], w2v, acc[il][hh]);
            }
        }

        #pragma unroll
        for (int il = 0; il < 4; il++)
            #pragma unroll
            for (int hh = 0; hh < 8; hh++)
                g_scores[((size_t)((b * NN + i0 + il) * HH + hh)) * NN + j] = acc[il][hh];
    }
}

// ---------------- warp reduce helpers ---------------------------------------------
__device__ __forceinline__ float warpMax(float v) {
    #pragma unroll
    for (int o = 16; o; o >>= 1) v = fmaxf(v, __shfl_xor_sync(0xFFFFFFFFu, v, o));
    return v;
}
__device__ __forceinline__ float warpSum(float v) {
    #pragma unroll
    for (int o = 16; o; o >>= 1) v += __shfl_xor_sync(0xFFFFFFFFu, v, o);
    return v;
}

// ---------------- fused softmax + AV (online phase 1, 8 i-rows per block) ---------
__global__ void __launch_bounds__(256) k_smav() {
    __shared__ float v_s[32 * 256];     // [jj][c]
    __shared__ float p_s[64 * 32];      // [row=il*8+h][jj]
    __shared__ float m_s[64], l_s[64];
    int bx = blockIdx.x;
    int b = bx >> 8;
    int i0 = (bx & 255) * 8;
    int tid = threadIdx.x;
    int wrp = tid >> 5, lane = tid & 31;

    // ---- phase 1: online per-row max + denominator, single scores read ----
    #pragma unroll
    for (int k = 0; k < 8; k++) {
        int row = k * 8 + wrp;          // il = k, h = wrp
        const float* ptr = g_scores + ((size_t)((b * NN + i0 + k) * HH + wrp)) * NN;
        float mx = -3.0e38f, sm = 0.0f;
        for (int j = lane; j < NN; j += 32) {
            float v = ptr[j];
            if (v > mx) { sm *= expf(mx - v); mx = v; }   // rare
            sm += expf(v - mx);
        }
        float gm = warpMax(mx);
        sm *= expf(mx - gm);
        sm = warpSum(sm);
        if (lane == 0) { m_s[row] = gm; l_s[row] = sm; }
    }
    __syncthreads();

    // ---- phase 2: AV with exp-on-the-fly ----
    int h = wrp;
    float acc[8];
    #pragma unroll
    for (int il = 0; il < 8; il++) acc[il] = 0.0f;

    for (int j0 = 0; j0 < NN; j0 += 32) {
        __syncthreads();
        #pragma unroll
        for (int k = 0; k < 32; k++) {
            int u = tid + k * 256;
            v_s[u] = g_v[(size_t)(b * NN + j0 + (u >> 8)) * DD + (u & 255)];
        }
        #pragma unroll
        for (int k = 0; k < 8; k++) {
            int u = tid + k * 256;
            int row = u >> 5, jj = u & 31;
            float sc = g_scores[((size_t)((b * NN + i0 + (row >> 3)) * HH + (row & 7))) * NN + j0 + jj];
            p_s[u] = expf(sc - m_s[row]);
        }
        __syncthreads();
        #pragma unroll 4
        for (int jj = 0; jj < 32; jj++) {
            float vv = v_s[jj * 256 + tid];
            #pragma unroll
            for (int il = 0; il < 8; il++)
                acc[il] = fmaf(p_s[(il * 8 + h) * 32 + jj], vv, acc[il]);
        }
    }
    #pragma unroll
    for (int il = 0; il < 8; il++)
        g_att[(size_t)(b * NN + i0 + il) * DD + tid] = acc[il] / l_s[il * 8 + h];
}

// ---------------- final Wo projection ---------------------------------------------
__global__ void k_out(float* __restrict__ out) {
    __shared__ float xs[8][256];
    int r0 = blockIdx.x * 8;
    int t = threadIdx.x;
    #pragma unroll
    for (int r = 0; r < 8; r++) xs[r][t] = g_att[(size_t)(r0 + r) * DD + t];
    __syncthreads();
    float acc[8];
    #pragma unroll
    for (int r = 0; r < 8; r++) acc[r] = 0.f;
    for (int c = 0; c < DD; c++) {
        float w = g_WoT[c * DD + t];
        #pragma unroll
        for (int r = 0; r < 8; r++) acc[r] = fmaf(xs[r][c], w, acc[r]);
    }
    #pragma unroll
    for (int r = 0; r < 8; r++) out[(size_t)(r0 + r) * DD + t] = acc[r];
}

// ---------------- launch ----------------------------------------------------------
extern "C" void kernel_launch(void* const* d_in, const int* in_sizes, int n_in,
                              void* d_out, int out_size) {
    const float* x  = (const float*)d_in[0];
    const float* R  = (const float*)d_in[1];
    const float* t  = (const float*)d_in[2];
    // d_in[3] = node_mask (all true)
    const float* Wq = (const float*)d_in[4];
    const float* Wk = (const float*)d_in[5];
    const float* Wv = (const float*)d_in[6];
    const float* Wo = (const float*)d_in[7];
    const float* W1 = (const float*)d_in[8];
    const float* b1 = (const float*)d_in[9];
    const float* W2 = (const float*)d_in[10];
    const float* b2 = (const float*)d_in[11];
    float* out = (float*)d_out;

    k_tables<<<128, 256>>>();
    k_trans<<<1024, 256>>>(Wq, Wk, Wv, Wo);
    k_zero<<<65, 256>>>();
    k_qkv<<<512, 256>>>(x);
    k_ktrans<<<dim3(64, 16), 256>>>();
    k_r<<<dim3(NN, BB), 256>>>(R, t);
    k_scanA<<<1, 32>>>();
    k_histB<<<1024, 256>>>();
    k_scanB<<<1, 32>>>();
    k_histC<<<1024, 256>>>();
    k_scanC<<<1, 32>>>();
    k_scores<<<dim3(NN / 4, BB), 256>>>(t, R, W1, b1, W2, b2);
    k_smav<<<512, 256>>>();
    k_out<<<512, 256>>>(out);
}